// round 15
// baseline (speedup 1.0000x reference)
#include <cuda_runtime.h>

// Problem constants (from reference)
#define BATCH   1024
#define NK      33          // ykinput rows = 33; nonzero support width (2*16+1)
#define COLBASE 4080        // VECCNTR - 1 - 15
#define VEC     8192
#define EPSF    0.01f

#define NBLOCKS 128         // one wave
#define NTHREADS 256        // 8 warps per block, one warp per batch row
#define WPB     8

__device__ float        g_total = 0.0f;
__device__ unsigned int g_count = 0;

__global__ void __launch_bounds__(NTHREADS)
ngl_kernel(const float* __restrict__ input,
           const float* __restrict__ output,
           const float* __restrict__ ykinput,
           float* __restrict__ out)
{
    __shared__ float yk_s[NK * NK];     // yk_s[k*33 + j] = ykinput[k, 4080+j]
    __shared__ float a_s[WPB][64];      // per-warp coefficient exchange
    __shared__ float wsum_s[WPB];

    const int tid  = threadIdx.x;
    const int warp = tid >> 5;
    const int lane = tid & 31;
    const int row  = blockIdx.x * WPB + warp;   // one warp per batch row

    // ---- Per-row parameter loads (issue early, overlap with tile load) ----
    const float4 in4 = *reinterpret_cast<const float4*>(input + row * 4);
    const float p0 = in4.x, p1 = in4.y, p2 = in4.z;
    const int   m  = (int)in4.w;                // 1..16, exact in fp32
    const float o0 = output[row * 3 + 0];
    const float o1 = output[row * 3 + 1];
    const float o2 = output[row * 3 + 2];

    // ---- Vectorized load of the 33x33 live slice of ykinput --------------
    // &ykinput[k*VEC + COLBASE] is 16B-aligned (COLBASE*4 = 16320, VEC*4 = 32768).
    // 33 rows x (8 float4 + 1 float) = 297 slots.
    for (int s = tid; s < NK * 9; s += NTHREADS) {
        const int k = s / 9;
        const int q = s - k * 9;
        const float* gsrc = ykinput + k * VEC + COLBASE;
        float* srow = &yk_s[k * NK];
        if (q < 8) {
            const float4 v = *reinterpret_cast<const float4*>(gsrc + 4 * q);
            srow[4 * q + 0] = v.x;
            srow[4 * q + 1] = v.y;
            srow[4 * q + 2] = v.z;
            srow[4 * q + 3] = v.w;
        } else {
            srow[32] = gsrc[32];
        }
    }

    // ---- Lane-distributed (m-1)-fold 3-tap convolution --------------------
    // c[j] = value at column COLBASE+j. Lane l owns e=c[2l], o=c[2l+1].
    float e = 0.0f, o = 0.0f;
    if (lane == 7) { o = p0; }               // c[15]
    if (lane == 8) { e = p1; o = p2; }       // c[16], c[17]

    for (int t = 0; t < m - 1; ++t) {
        float o_up = __shfl_up_sync(0xffffffffu, o, 1);   // c[2l-1]
        float e_dn = __shfl_down_sync(0xffffffffu, e, 1); // c[2l+2]
        if (lane == 0)  o_up = 0.0f;
        if (lane == 31) e_dn = 0.0f;
        float e_new = fmaf(p0, o_up, fmaf(p1, e, p2 * o));
        float o_new = fmaf(p0, e,    fmaf(p1, o, p2 * e_dn));
        e = e_new;
        o = o_new;
    }

    a_s[warp][2 * lane]     = e;
    a_s[warp][2 * lane + 1] = o;
    __syncthreads();    // covers yk_s fill AND per-warp coefficient exchange

    // ---- Hoist coefficients into registers (broadcast LDS) ----------------
    float areg[NK];
    #pragma unroll
    for (int j = 0; j < NK; ++j) areg[j] = a_s[warp][j];

    // ---- Lane-parallel over k: phim_y, psi_y, rational loss term ----------
    float lsum = 0.0f;
    for (int k = lane; k < NK; k += 32) {     // lane 0 also does k=32
        const float* y = &yk_s[k * NK];       // stride 33 across lanes: conflict-free
        float pa = 0.0f, pb = 0.0f;           // dual accumulators: halve dep chain
        #pragma unroll
        for (int j = 0; j < 32; j += 2) {
            pa = fmaf(areg[j],     y[j],     pa);
            pb = fmaf(areg[j + 1], y[j + 1], pb);
        }
        pa = fmaf(areg[32], y[32], pa);
        const float p = pa + pb;
        const float psi = fmaf(o0, y[15], fmaf(o1, y[16], o2 * y[17]));
        const float d = p - psi;
        const float q = 1.0f - p;
        lsum += __fdividef(d * d, fmaf(q, q, EPSF));
    }

    // ---- Deterministic warp reduction --------------------------------------
    #pragma unroll
    for (int off = 16; off; off >>= 1)
        lsum += __shfl_down_sync(0xffffffffu, lsum, off);
    if (lane == 0)
        wsum_s[warp] = lsum;
    __syncthreads();

    // ---- Lean global tail: one atomic accumulate per block -----------------
    if (tid == 0) {
        float bs = 0.0f;
        #pragma unroll
        for (int w = 0; w < WPB; ++w) bs += wsum_s[w];
        atomicAdd(&g_total, bs);
        __threadfence();                      // release: my add before my count
        unsigned int old = atomicAdd(&g_count, 1u);
        if (old == (unsigned int)(NBLOCKS - 1)) {
            // All 128 float-adds are ordered before their blocks' count-adds;
            // a single atomicExch reads the final total AND re-arms in one op.
            *out = atomicExch(&g_total, 0.0f);
            g_count = 0u;                     // re-arm counter for next replay
        }
    }
}

extern "C" void kernel_launch(void* const* d_in, const int* in_sizes, int n_in,
                              void* d_out, int out_size)
{
    const float* input   = (const float*)d_in[0];   // (1024, 4)
    const float* output  = (const float*)d_in[1];   // (1024, 3)
    const float* ykinput = (const float*)d_in[2];   // (33, 8192)
    float* out = (float*)d_out;                     // scalar loss
    (void)in_sizes; (void)n_in; (void)out_size;

    ngl_kernel<<<NBLOCKS, NTHREADS>>>(input, output, ykinput, out);
}

// round 16
// speedup vs baseline: 1.0333x; 1.0333x over previous
#include <cuda_runtime.h>

// Problem constants (from reference)
#define BATCH   1024
#define NK      33          // ykinput rows = 33; nonzero support width (2*16+1)
#define COLBASE 4080        // VECCNTR - 1 - 15
#define VEC     8192
#define EPSF    0.01f

#define NBLOCKS 128         // one wave
#define NTHREADS 256        // 8 warps per block, one warp per batch row
#define WPB     8

__device__ float        g_total = 0.0f;
__device__ unsigned int g_count = 0;

__global__ void __launch_bounds__(NTHREADS)
ngl_kernel(const float* __restrict__ input,
           const float* __restrict__ output,
           const float* __restrict__ ykinput,
           float* __restrict__ out)
{
    __shared__ float yk_s[NK * NK];     // yk_s[k*33 + j] = ykinput[k, 4080+j]
    __shared__ float a_s[WPB][64];      // per-warp coefficient exchange
    __shared__ float wsum_s[WPB];

    const int tid  = threadIdx.x;
    const int warp = tid >> 5;
    const int lane = tid & 31;
    const int row  = blockIdx.x * WPB + warp;   // one warp per batch row

    // ---- Per-row parameter loads (issue early, overlap with tile load) ----
    const float4 in4 = *reinterpret_cast<const float4*>(input + row * 4);
    const float p0 = in4.x, p1 = in4.y, p2 = in4.z;
    const int   m  = (int)in4.w;                // 1..16, exact in fp32
    const float o0 = output[row * 3 + 0];
    const float o1 = output[row * 3 + 1];
    const float o2 = output[row * 3 + 2];

    // ---- Vectorized load of the 33x33 live slice of ykinput --------------
    // &ykinput[k*VEC + COLBASE] is 16B-aligned (COLBASE*4 = 16320, VEC*4 = 32768).
    // 33 rows x (8 float4 + 1 float) = 297 slots.
    for (int s = tid; s < NK * 9; s += NTHREADS) {
        const int k = s / 9;
        const int q = s - k * 9;
        const float* gsrc = ykinput + k * VEC + COLBASE;
        float* srow = &yk_s[k * NK];
        if (q < 8) {
            const float4 v = *reinterpret_cast<const float4*>(gsrc + 4 * q);
            srow[4 * q + 0] = v.x;
            srow[4 * q + 1] = v.y;
            srow[4 * q + 2] = v.z;
            srow[4 * q + 3] = v.w;
        } else {
            srow[32] = gsrc[32];
        }
    }

    // ---- Lane-distributed (m-1)-fold 3-tap convolution --------------------
    // c[j] = value at column COLBASE+j. Lane l owns e=c[2l], o=c[2l+1].
    float e = 0.0f, o = 0.0f;
    if (lane == 7) { o = p0; }               // c[15]
    if (lane == 8) { e = p1; o = p2; }       // c[16], c[17]

    for (int t = 0; t < m - 1; ++t) {
        float o_up = __shfl_up_sync(0xffffffffu, o, 1);   // c[2l-1]
        float e_dn = __shfl_down_sync(0xffffffffu, e, 1); // c[2l+2]
        if (lane == 0)  o_up = 0.0f;
        if (lane == 31) e_dn = 0.0f;
        float e_new = fmaf(p0, o_up, fmaf(p1, e, p2 * o));
        float o_new = fmaf(p0, e,    fmaf(p1, o, p2 * e_dn));
        e = e_new;
        o = o_new;
    }

    a_s[warp][2 * lane]     = e;
    a_s[warp][2 * lane + 1] = o;
    __syncthreads();    // covers yk_s fill AND per-warp coefficient exchange

    // ---- Hoist coefficients into registers (broadcast LDS) ----------------
    float areg[NK];
    #pragma unroll
    for (int j = 0; j < NK; ++j) areg[j] = a_s[warp][j];

    // ---- Lane-parallel over k: phim_y, psi_y, rational loss term ----------
    float lsum = 0.0f;
    for (int k = lane; k < NK; k += 32) {     // lane 0 also does k=32
        const float* y = &yk_s[k * NK];       // stride 33 across lanes: conflict-free
        float pa = 0.0f, pb = 0.0f;           // dual accumulators: halve dep chain
        #pragma unroll
        for (int j = 0; j < 32; j += 2) {
            pa = fmaf(areg[j],     y[j],     pa);
            pb = fmaf(areg[j + 1], y[j + 1], pb);
        }
        pa = fmaf(areg[32], y[32], pa);
        const float p = pa + pb;
        const float psi = fmaf(o0, y[15], fmaf(o1, y[16], o2 * y[17]));
        const float d = p - psi;
        const float q = 1.0f - p;
        lsum += __fdividef(d * d, fmaf(q, q, EPSF));
    }

    // ---- Deterministic warp reduction --------------------------------------
    #pragma unroll
    for (int off = 16; off; off >>= 1)
        lsum += __shfl_down_sync(0xffffffffu, lsum, off);
    if (lane == 0)
        wsum_s[warp] = lsum;
    __syncthreads();

    // ---- Lean global tail: one atomic accumulate per block -----------------
    if (tid == 0) {
        float bs = 0.0f;
        #pragma unroll
        for (int w = 0; w < WPB; ++w) bs += wsum_s[w];
        atomicAdd(&g_total, bs);
        __threadfence();                      // release: my add before my count
        unsigned int old = atomicAdd(&g_count, 1u);
        if (old == (unsigned int)(NBLOCKS - 1)) {
            // All 128 float-adds are ordered before their blocks' count-adds;
            // a single atomicExch reads the final total AND re-arms in one op.
            *out = atomicExch(&g_total, 0.0f);
            g_count = 0u;                     // re-arm counter for next replay
        }
    }
}

extern "C" void kernel_launch(void* const* d_in, const int* in_sizes, int n_in,
                              void* d_out, int out_size)
{
    const float* input   = (const float*)d_in[0];   // (1024, 4)
    const float* output  = (const float*)d_in[1];   // (1024, 3)
    const float* ykinput = (const float*)d_in[2];   // (33, 8192)
    float* out = (float*)d_out;                     // scalar loss
    (void)in_sizes; (void)n_in; (void)out_size;

    ngl_kernel<<<NBLOCKS, NTHREADS>>>(input, output, ykinput, out);
}

// round 17
// speedup vs baseline: 1.0449x; 1.0112x over previous
#include <cuda_runtime.h>

// Problem constants (from reference)
#define BATCH   1024
#define NK      33          // ykinput rows = 33; nonzero support width (2*16+1)
#define COLBASE 4080        // VECCNTR - 1 - 15
#define VEC     8192
#define EPSF    0.01f

#define NBLOCKS 128         // one wave
#define NTHREADS 256        // 8 warps per block, one warp per batch row
#define WPB     8

__device__ float        g_total = 0.0f;
__device__ unsigned int g_count = 0;

__global__ void __launch_bounds__(NTHREADS)
ngl_kernel(const float* __restrict__ input,
           const float* __restrict__ output,
           const float* __restrict__ ykinput,
           float* __restrict__ out)
{
    __shared__ float yk_s[NK * NK];     // yk_s[k*33 + j] = ykinput[k, 4080+j]
    __shared__ float a_s[WPB][64];      // per-warp coefficient exchange
    __shared__ float wsum_s[WPB];

    const int tid  = threadIdx.x;
    const int warp = tid >> 5;
    const int lane = tid & 31;
    const int row  = blockIdx.x * WPB + warp;   // one warp per batch row

    // ---- Per-row parameter loads (issue early, overlap with tile load) ----
    const float4 in4 = *reinterpret_cast<const float4*>(input + row * 4);
    const float p0 = in4.x, p1 = in4.y, p2 = in4.z;
    const int   m  = (int)in4.w;                // 1..16, exact in fp32
    const float o0 = output[row * 3 + 0];
    const float o1 = output[row * 3 + 1];
    const float o2 = output[row * 3 + 2];

    // ---- Vectorized load of the 33x33 live slice of ykinput --------------
    // &ykinput[k*VEC + COLBASE] is 16B-aligned (COLBASE*4 = 16320, VEC*4 = 32768).
    // 33 rows x (8 float4 + 1 float) = 297 slots.
    for (int s = tid; s < NK * 9; s += NTHREADS) {
        const int k = s / 9;
        const int q = s - k * 9;
        const float* gsrc = ykinput + k * VEC + COLBASE;
        float* srow = &yk_s[k * NK];
        if (q < 8) {
            const float4 v = *reinterpret_cast<const float4*>(gsrc + 4 * q);
            srow[4 * q + 0] = v.x;
            srow[4 * q + 1] = v.y;
            srow[4 * q + 2] = v.z;
            srow[4 * q + 3] = v.w;
        } else {
            srow[32] = gsrc[32];
        }
    }

    // ---- Lane-distributed (m-1)-fold 3-tap convolution --------------------
    // c[j] = value at column COLBASE+j. Lane l owns e=c[2l], o=c[2l+1].
    float e = 0.0f, o = 0.0f;
    if (lane == 7) { o = p0; }               // c[15]
    if (lane == 8) { e = p1; o = p2; }       // c[16], c[17]

    for (int t = 0; t < m - 1; ++t) {
        float o_up = __shfl_up_sync(0xffffffffu, o, 1);   // c[2l-1]
        float e_dn = __shfl_down_sync(0xffffffffu, e, 1); // c[2l+2]
        if (lane == 0)  o_up = 0.0f;
        if (lane == 31) e_dn = 0.0f;
        float e_new = fmaf(p0, o_up, fmaf(p1, e, p2 * o));
        float o_new = fmaf(p0, e,    fmaf(p1, o, p2 * e_dn));
        e = e_new;
        o = o_new;
    }

    a_s[warp][2 * lane]     = e;
    a_s[warp][2 * lane + 1] = o;
    __syncthreads();    // covers yk_s fill AND per-warp coefficient exchange

    // ---- Hoist coefficients into registers (broadcast LDS) ----------------
    float areg[NK];
    #pragma unroll
    for (int j = 0; j < NK; ++j) areg[j] = a_s[warp][j];

    // ---- Lane-parallel over k: phim_y, psi_y, rational loss term ----------
    float lsum = 0.0f;
    for (int k = lane; k < NK; k += 32) {     // lane 0 also does k=32
        const float* y = &yk_s[k * NK];       // stride 33 across lanes: conflict-free
        float pa = 0.0f, pb = 0.0f;           // dual accumulators: halve dep chain
        #pragma unroll
        for (int j = 0; j < 32; j += 2) {
            pa = fmaf(areg[j],     y[j],     pa);
            pb = fmaf(areg[j + 1], y[j + 1], pb);
        }
        pa = fmaf(areg[32], y[32], pa);
        const float p = pa + pb;
        const float psi = fmaf(o0, y[15], fmaf(o1, y[16], o2 * y[17]));
        const float d = p - psi;
        const float q = 1.0f - p;
        lsum += __fdividef(d * d, fmaf(q, q, EPSF));
    }

    // ---- Deterministic warp reduction --------------------------------------
    #pragma unroll
    for (int off = 16; off; off >>= 1)
        lsum += __shfl_down_sync(0xffffffffu, lsum, off);
    if (lane == 0)
        wsum_s[warp] = lsum;
    __syncthreads();

    // ---- Lean global tail: one atomic accumulate per block -----------------
    if (tid == 0) {
        float bs = 0.0f;
        #pragma unroll
        for (int w = 0; w < WPB; ++w) bs += wsum_s[w];
        atomicAdd(&g_total, bs);
        __threadfence();                      // release: my add before my count
        unsigned int old = atomicAdd(&g_count, 1u);
        if (old == (unsigned int)(NBLOCKS - 1)) {
            // All 128 float-adds are ordered before their blocks' count-adds;
            // a single atomicExch reads the final total AND re-arms in one op.
            *out = atomicExch(&g_total, 0.0f);
            g_count = 0u;                     // re-arm counter for next replay
        }
    }
}

extern "C" void kernel_launch(void* const* d_in, const int* in_sizes, int n_in,
                              void* d_out, int out_size)
{
    const float* input   = (const float*)d_in[0];   // (1024, 4)
    const float* output  = (const float*)d_in[1];   // (1024, 3)
    const float* ykinput = (const float*)d_in[2];   // (33, 8192)
    float* out = (float*)d_out;                     // scalar loss
    (void)in_sizes; (void)n_in; (void)out_size;

    ngl_kernel<<<NBLOCKS, NTHREADS>>>(input, output, ykinput, out);
}